// round 7
// baseline (speedup 1.0000x reference)
#include <cuda_runtime.h>
#include <cuda_fp16.h>
#include <math.h>
#include <stdint.h>

// Problem constants
#define BATCH 2
#define SEQ   2048
#define EMB   2048
#define HEADS 16
#define HDIM  128

// Scratch buffers (allocation-free rule: __device__ globals)
__device__ float  g_q[BATCH * SEQ * EMB];
__device__ float  g_k[BATCH * SEQ * EMB];
__device__ float  g_v[BATCH * SEQ * EMB];
__device__ __half g_acth[BATCH * SEQ * EMB];  // fp16 activations
__device__ __half g_atth[BATCH * SEQ * EMB];  // fp16 attention output
__device__ __half g_wqh[EMB * EMB];
__device__ __half g_wkh[EMB * EMB];
__device__ __half g_wvh[EMB * EMB];
__device__ __half g_woh[EMB * EMB];

// ---------------------------------------------------------------------------
// helpers
// ---------------------------------------------------------------------------
__device__ __forceinline__ uint32_t smem_u32(const void* p) {
    uint32_t a;
    asm("{ .reg .u64 t; cvta.to.shared.u64 t, %1; cvt.u32.u64 %0, t; }"
        : "=r"(a) : "l"(p));
    return a;
}

__device__ __forceinline__ float ex2(float x) {
    float r;
    asm("ex2.approx.ftz.f32 %0, %1;" : "=f"(r) : "f"(x));
    return r;
}

__device__ __forceinline__ uint32_t h2u(__half2 h) {
    return *reinterpret_cast<uint32_t*>(&h);
}

#define CP_ASYNC16(saddr, gaddr) \
    asm volatile("cp.async.ca.shared.global [%0], [%1], 16;" \
                 :: "r"(saddr), "l"(gaddr) : "memory")
#define CP_COMMIT() asm volatile("cp.async.commit_group;" ::: "memory")
#define CP_WAIT(n)  asm volatile("cp.async.wait_group %0;" :: "n"(n) : "memory")

#define MMA_F16(c, a0, a1, a2, a3, b0, b1) \
    asm volatile("mma.sync.aligned.m16n8k16.row.col.f32.f16.f16.f32 " \
                 "{%0,%1,%2,%3}, {%4,%5,%6,%7}, {%8,%9}, {%0,%1,%2,%3};" \
                 : "+f"((c)[0]), "+f"((c)[1]), "+f"((c)[2]), "+f"((c)[3]) \
                 : "r"(a0), "r"(a1), "r"(a2), "r"(a3), "r"(b0), "r"(b1))

// ---------------------------------------------------------------------------
// fused fp32 -> fp16 conversion for activations + the 4 weights
// ---------------------------------------------------------------------------
__global__ __launch_bounds__(256)
void cvt_f16_all(const float* __restrict__ act,
                 const float* __restrict__ wq, const float* __restrict__ wk,
                 const float* __restrict__ wv, const float* __restrict__ wo) {
    int blk = blockIdx.x;
    const float* src;
    __half* dst;
    size_t base;
    if (blk < 4096) {
        src = act; dst = g_acth; base = (size_t)blk * 2048;
    } else {
        int wb = blk - 4096;
        int w = wb >> 11;
        int bb = wb & 2047;
        base = (size_t)bb * 2048;
        if (w == 0)      { src = wq; dst = g_wqh; }
        else if (w == 1) { src = wk; dst = g_wkh; }
        else if (w == 2) { src = wv; dst = g_wvh; }
        else             { src = wo; dst = g_woh; }
    }
    size_t idx = base + (size_t)threadIdx.x * 8;
    float4 v0 = *(const float4*)(src + idx);
    float4 v1 = *(const float4*)(src + idx + 4);
    uint4 o;
    o.x = h2u(__floats2half2_rn(v0.x, v0.y));
    o.y = h2u(__floats2half2_rn(v0.z, v0.w));
    o.z = h2u(__floats2half2_rn(v1.x, v1.y));
    o.w = h2u(__floats2half2_rn(v1.z, v1.w));
    *(uint4*)(dst + idx) = o;
}

// ---------------------------------------------------------------------------
// fp16 mma.sync GEMM (NT), unchanged from R6 except full-M launch.
// ---------------------------------------------------------------------------
#define BM 128
#define BN 128
#define BKH 32
#define SROW 20
#define TILE_U (128 * SROW)
#define STAGE_U (2 * TILE_U)
#define STAGE_B (STAGE_U * 4)
#define GM_STAGES 4
#define GM_SMEM (GM_STAGES * STAGE_B)
#define NK (EMB / BKH)

__global__ __launch_bounds__(256, 2)
void gemm_f16(const __half* __restrict__ A, const __half* __restrict__ B,
              float* __restrict__ C) {
    extern __shared__ uint32_t smu[];
    const uint32_t sb = smem_u32(smu);

    const int tid = threadIdx.x;
    const int wid = tid >> 5;
    const int lane = tid & 31;
    const int gid = lane >> 2;
    const int tig = lane & 3;
    const int wm = wid >> 2;
    const int wn = wid & 3;
    const int bm = blockIdx.y * BM;
    const int bn = blockIdx.x * BN;

    float acc[4][4][4];
#pragma unroll
    for (int mi = 0; mi < 4; mi++)
#pragma unroll
        for (int ni = 0; ni < 4; ni++)
#pragma unroll
            for (int q = 0; q < 4; q++) acc[mi][ni][q] = 0.0f;

    auto issue_stage = [&](int kt, int stage) {
        const uint32_t sbase = sb + stage * STAGE_B;
#pragma unroll
        for (int c = 0; c < 2; c++) {
            int id = tid + c * 256;
            int row = id >> 2;
            int cg = id & 3;
            uint32_t soff = (uint32_t)(row * SROW + cg * 4) * 4u;
            const __half* gaA = A + (size_t)(bm + row) * EMB + kt * BKH + cg * 8;
            const __half* gaB = B + (size_t)(bn + row) * EMB + kt * BKH + cg * 8;
            CP_ASYNC16(sbase + soff, gaA);
            CP_ASYNC16(sbase + TILE_U * 4 + soff, gaB);
        }
        CP_COMMIT();
    };

    issue_stage(0, 0);
    issue_stage(1, 1);
    issue_stage(2, 2);

    for (int kt = 0; kt < NK; kt++) {
        const int s = kt & 3;
        if (kt + 3 < NK) { CP_WAIT(2); } else if (kt + 2 < NK) { CP_WAIT(1); } else { CP_WAIT(0); }
        __syncthreads();

        const uint32_t* As = smu + s * STAGE_U;
        const uint32_t* Bs = As + TILE_U;
        const int am0 = wm * 64;
        const int bn0 = wn * 32;

#pragma unroll
        for (int ks = 0; ks < 2; ks++) {
            const int k0 = ks * 8;
            uint32_t a[4][4];
#pragma unroll
            for (int mi = 0; mi < 4; mi++) {
                const int r0 = am0 + mi * 16 + gid;
                a[mi][0] = As[r0 * SROW + k0 + tig];
                a[mi][1] = As[(r0 + 8) * SROW + k0 + tig];
                a[mi][2] = As[r0 * SROW + k0 + tig + 4];
                a[mi][3] = As[(r0 + 8) * SROW + k0 + tig + 4];
            }
            uint32_t b[4][2];
#pragma unroll
            for (int ni = 0; ni < 4; ni++) {
                const int n0 = bn0 + ni * 8 + gid;
                b[ni][0] = Bs[n0 * SROW + k0 + tig];
                b[ni][1] = Bs[n0 * SROW + k0 + tig + 4];
            }
#pragma unroll
            for (int mi = 0; mi < 4; mi++)
#pragma unroll
                for (int ni = 0; ni < 4; ni++)
                    MMA_F16(acc[mi][ni], a[mi][0], a[mi][1], a[mi][2], a[mi][3],
                            b[ni][0], b[ni][1]);
        }
        if (kt + 3 < NK) issue_stage(kt + 3, (kt + 3) & 3);
    }

#pragma unroll
    for (int mi = 0; mi < 4; mi++) {
        const int r0 = bm + wm * 64 + mi * 16 + gid;
#pragma unroll
        for (int ni = 0; ni < 4; ni++) {
            const int c0 = bn + wn * 32 + ni * 8 + tig * 2;
            float2 w0; w0.x = acc[mi][ni][0]; w0.y = acc[mi][ni][1];
            float2 w1; w1.x = acc[mi][ni][2]; w1.y = acc[mi][ni][3];
            *(float2*)(C + (size_t)r0 * EMB + c0) = w0;
            *(float2*)(C + (size_t)(r0 + 8) * EMB + c0) = w1;
        }
    }
}

// ---------------------------------------------------------------------------
// xpos rotary on q and k (in place, fp32).
// ---------------------------------------------------------------------------
__global__ __launch_bounds__(256)
void xpos_kernel() {
    int idx = blockIdx.x * 256 + threadIdx.x;
    int pair = idx & 63;
    int h = (idx >> 6) & (HEADS - 1);
    int bs = idx >> 10;
    int s = bs & (SEQ - 1);

    float seq = (float)(s - SEQ / 2) * (1.0f / 512.0f);
    float dr = 2.0f * (float)(pair + 1);
    float theta = powf(1.0e-4f, dr * (1.0f / 128.0f));
    float zeta = (dr * (1.0f / 64.0f) + 51.2f) * (1.0f / 52.2f);
    float ang = seq * theta;
    float c = cosf(ang);
    float sn = sinf(ang);
    float t = powf(zeta, seq);
    float it = 1.0f / t;

    size_t base = (size_t)bs * EMB + h * HDIM + pair * 2;
    float2 qv = *(float2*)(g_q + base);
    float2 kv = *(float2*)(g_k + base);
    float2 qo, ko;
    qo.x = (qv.x * c - qv.y * sn) * t;
    qo.y = (qv.y * c + qv.x * sn) * t;
    ko.x = (kv.x * c - kv.y * sn) * it;
    ko.y = (kv.y * c + kv.x * sn) * it;
    *(float2*)(g_q + base) = qo;
    *(float2*)(g_k + base) = ko;
}

// ---------------------------------------------------------------------------
// Causal flash attention, fp32, triangle-paired for load balance.
// CTA = 256 threads = 64 query rows x 4-thread groups.
// Each CTA processes q-tiles p and 31-p (64 rows each) -> constant work.
// Grid = 32 bh x 16 pairs = 512 CTAs, 3 CTAs/SM resident.
// ---------------------------------------------------------------------------
__global__ __launch_bounds__(256, 3)
void attn_kernel() {
    extern __shared__ float smf[];
    float4* Ks4 = (float4*)smf;                 // [64][32] float4
    float4* Vs4 = (float4*)(smf + 64 * 128);

    const int bid = blockIdx.x;
    const int bh = bid >> 4;       // 0..31
    const int pr = bid & 15;       // pair 0..15
    const int b = bh >> 4;
    const int h = bh & (HEADS - 1);

    const int tid = threadIdx.x;
    const int rloc = tid >> 2;     // 0..63
    const int g = tid & 3;
    const unsigned gmask = 0xFu << ((tid & 31) & ~3);

    const float qscale = 0.08838834764831845f * 1.4426950408889634f;
    const float* kg = g_k + (size_t)b * SEQ * EMB + h * HDIM;
    const float* vg = g_v + (size_t)b * SEQ * EMB + h * HDIM;

#pragma unroll 1
    for (int half = 0; half < 2; half++) {
        const int qt = half ? (31 - pr) : pr;   // 64-row q-tile index
        const int r = qt * 64 + rloc;

        const float* qbase = g_q + ((size_t)b * SEQ + r) * EMB + h * HDIM + g * 32;
        float4 q4[8];
#pragma unroll
        for (int i = 0; i < 8; i++) {
            float4 v = ((const float4*)qbase)[i];
            v.x *= qscale; v.y *= qscale; v.z *= qscale; v.w *= qscale;
            q4[i] = v;
        }

        float4 o4[8];
#pragma unroll
        for (int i = 0; i < 8; i++) o4[i] = make_float4(0.f, 0.f, 0.f, 0.f);
        float m = -1.0e30f, l = 0.0f;

        const int nkt = qt + 1;     // 64-key tiles covering [0, qt*64+64)
        for (int kt = 0; kt < nkt; kt++) {
            __syncthreads();
            // load 64-key K/V tile: 2048 float4, 256 threads -> 8 each
#pragma unroll
            for (int i = 0; i < 8; i++) {
                int id = tid + i * 256;
                int row = id >> 5;
                int c4 = id & 31;
                size_t goff = (size_t)(kt * 64 + row) * EMB + c4 * 4;
                Ks4[row * 32 + c4] = *(const float4*)(kg + goff);
                Vs4[row * 32 + c4] = *(const float4*)(vg + goff);
            }
            __syncthreads();

            int jmax = r - kt * 64 + 1;
            if (jmax > 64) jmax = 64;

            for (int j0 = 0; j0 < jmax; j0 += 4) {
                float pp[4];
#pragma unroll
                for (int jj = 0; jj < 4; jj++) {
                    const float4* krow = Ks4 + (j0 + jj) * 32 + g * 8;
                    float p0 = 0.f, p1 = 0.f, p2 = 0.f, p3 = 0.f;
#pragma unroll
                    for (int i = 0; i < 8; i++) {
                        float4 kv = krow[i];
                        p0 = fmaf(q4[i].x, kv.x, p0);
                        p1 = fmaf(q4[i].y, kv.y, p1);
                        p2 = fmaf(q4[i].z, kv.z, p2);
                        p3 = fmaf(q4[i].w, kv.w, p3);
                    }
                    pp[jj] = (p0 + p1) + (p2 + p3);
                }
                float x0 = __shfl_xor_sync(gmask, pp[0], 1);
                float x1 = __shfl_xor_sync(gmask, pp[1], 1);
                float x2 = __shfl_xor_sync(gmask, pp[2], 1);
                float x3 = __shfl_xor_sync(gmask, pp[3], 1);
                bool odd = (g & 1);
                float ka = odd ? (pp[1] + x1) : (pp[0] + x0);
                float kb = odd ? (pp[3] + x3) : (pp[2] + x2);
                float ya = __shfl_xor_sync(gmask, ka, 2);
                float yb = __shfl_xor_sync(gmask, kb, 2);
                float s = (g & 2) ? (kb + yb) : (ka + ya);
                if (j0 + g >= jmax) s = -1.0e30f;

                float mx = fmaxf(s, __shfl_xor_sync(gmask, s, 1));
                mx = fmaxf(mx, __shfl_xor_sync(gmask, mx, 2));
                float mn = fmaxf(m, mx);
                float cf = ex2(m - mn);
                float p = ex2(s - mn);
                m = mn;

                float q1 = __shfl_xor_sync(gmask, p, 1);
                float q2 = __shfl_xor_sync(gmask, p, 2);
                float q3 = __shfl_xor_sync(gmask, q1, 2);
                l = l * cf + ((p + q1) + (q2 + q3));

                const float4* v0 = Vs4 + (j0 + g) * 32 + g * 8;
                const float4* v1 = Vs4 + (j0 + (g ^ 1)) * 32 + g * 8;
                const float4* v2 = Vs4 + (j0 + (g ^ 2)) * 32 + g * 8;
                const float4* v3 = Vs4 + (j0 + (g ^ 3)) * 32 + g * 8;
#pragma unroll
                for (int i = 0; i < 8; i++) {
                    float4 a0 = v0[i], a1 = v1[i], a2 = v2[i], a3 = v3[i];
                    float4 oo = o4[i];
                    oo.x = oo.x * cf; oo.y = oo.y * cf;
                    oo.z = oo.z * cf; oo.w = oo.w * cf;
                    oo.x = fmaf(p, a0.x, oo.x); oo.y = fmaf(p, a0.y, oo.y);
                    oo.z = fmaf(p, a0.z, oo.z); oo.w = fmaf(p, a0.w, oo.w);
                    oo.x = fmaf(q1, a1.x, oo.x); oo.y = fmaf(q1, a1.y, oo.y);
                    oo.z = fmaf(q1, a1.z, oo.z); oo.w = fmaf(q1, a1.w, oo.w);
                    oo.x = fmaf(q2, a2.x, oo.x); oo.y = fmaf(q2, a2.y, oo.y);
                    oo.z = fmaf(q2, a2.z, oo.z); oo.w = fmaf(q2, a2.w, oo.w);
                    oo.x = fmaf(q3, a3.x, oo.x); oo.y = fmaf(q3, a3.y, oo.y);
                    oo.z = fmaf(q3, a3.z, oo.z); oo.w = fmaf(q3, a3.w, oo.w);
                    o4[i] = oo;
                }
            }
        }

        float inv = 1.0f / l;
        __half2* ob2 = (__half2*)(g_atth + ((size_t)b * SEQ + r) * EMB + h * HDIM + g * 32);
#pragma unroll
        for (int i = 0; i < 8; i++) {
            ob2[i * 2 + 0] = __floats2half2_rn(o4[i].x * inv, o4[i].y * inv);
            ob2[i * 2 + 1] = __floats2half2_rn(o4[i].z * inv, o4[i].w * inv);
        }
        __syncthreads();   // smem reuse barrier between the two passes
    }
}

// ---------------------------------------------------------------------------
// Launch. Order: cvt, Q, K, xpos, V, attn (6th: ncu capture), O.
// ---------------------------------------------------------------------------
extern "C" void kernel_launch(void* const* d_in, const int* in_sizes, int n_in,
                              void* d_out, int out_size) {
    const float* act = (const float*)d_in[0];
    const float* Wq  = (const float*)d_in[1];
    const float* Wk  = (const float*)d_in[2];
    const float* Wv  = (const float*)d_in[3];
    const float* Wo  = (const float*)d_in[4];
    float* out = (float*)d_out;

    float *qp, *kp, *vp;
    __half *acth, *atth, *wqh, *wkh, *wvh, *woh;
    cudaGetSymbolAddress((void**)&qp, g_q);
    cudaGetSymbolAddress((void**)&kp, g_k);
    cudaGetSymbolAddress((void**)&vp, g_v);
    cudaGetSymbolAddress((void**)&acth, g_acth);
    cudaGetSymbolAddress((void**)&atth, g_atth);
    cudaGetSymbolAddress((void**)&wqh, g_wqh);
    cudaGetSymbolAddress((void**)&wkh, g_wkh);
    cudaGetSymbolAddress((void**)&wvh, g_wvh);
    cudaGetSymbolAddress((void**)&woh, g_woh);

    cudaFuncSetAttribute(gemm_f16, cudaFuncAttributeMaxDynamicSharedMemorySize, GM_SMEM);
    cudaFuncSetAttribute(attn_kernel, cudaFuncAttributeMaxDynamicSharedMemorySize,
                         64 * 128 * 4 * 2);

    dim3 ggrid(EMB / BN, BATCH * SEQ / BM);   // (16, 32)

    // 1: conversions
    cvt_f16_all<<<4096 + 4 * 2048, 256>>>(act, Wq, Wk, Wv, Wo);
    // 2-3: Q, K GEMMs
    gemm_f16<<<ggrid, 256, GM_SMEM>>>(acth, wqh, qp);
    gemm_f16<<<ggrid, 256, GM_SMEM>>>(acth, wkh, kp);
    // 4: xpos (needs q,k)
    int nrot = BATCH * SEQ * HEADS * 64;
    xpos_kernel<<<nrot / 256, 256>>>();
    // 5: V GEMM
    gemm_f16<<<ggrid, 256, GM_SMEM>>>(acth, wvh, vp);
    // 6: attention (ncu capture target)
    attn_kernel<<<32 * 16, 256, 64 * 128 * 4 * 2>>>();
    // 7: output GEMM
    gemm_f16<<<ggrid, 256, GM_SMEM>>>(atth, woh, out);
}

// round 8
// speedup vs baseline: 12.9654x; 12.9654x over previous
#include <cuda_runtime.h>
#include <cuda_fp16.h>
#include <math.h>
#include <stdint.h>

// Problem constants
#define BATCH 2
#define SEQ   2048
#define EMB   2048
#define HEADS 16
#define HDIM  128

// Scratch buffers (allocation-free rule: __device__ globals)
__device__ float  g_q[BATCH * SEQ * EMB];     // Q GEMM out (fp32, pre-xpos)
__device__ float  g_k[BATCH * SEQ * EMB];
__device__ float  g_v[BATCH * SEQ * EMB];
__device__ __half g_acth[BATCH * SEQ * EMB];  // fp16 activations
__device__ __half g_atth[BATCH * SEQ * EMB];  // fp16 attention output
__device__ __half g_qh[BATCH * SEQ * EMB];    // fp16 rotated+scaled Q
__device__ __half g_kh[BATCH * SEQ * EMB];    // fp16 rotated K
__device__ __half g_vth[32 * HDIM * SEQ];     // fp16 V transposed per (b,h)
__device__ __half g_wqh[EMB * EMB];
__device__ __half g_wkh[EMB * EMB];
__device__ __half g_wvh[EMB * EMB];
__device__ __half g_woh[EMB * EMB];

// ---------------------------------------------------------------------------
// helpers
// ---------------------------------------------------------------------------
__device__ __forceinline__ uint32_t smem_u32(const void* p) {
    uint32_t a;
    asm("{ .reg .u64 t; cvta.to.shared.u64 t, %1; cvt.u32.u64 %0, t; }"
        : "=r"(a) : "l"(p));
    return a;
}

__device__ __forceinline__ float ex2(float x) {
    float r;
    asm("ex2.approx.ftz.f32 %0, %1;" : "=f"(r) : "f"(x));
    return r;
}

__device__ __forceinline__ uint32_t h2u(__half2 h) {
    return *reinterpret_cast<uint32_t*>(&h);
}

#define CP_ASYNC16(saddr, gaddr) \
    asm volatile("cp.async.ca.shared.global [%0], [%1], 16;" \
                 :: "r"(saddr), "l"(gaddr) : "memory")
#define CP_COMMIT() asm volatile("cp.async.commit_group;" ::: "memory")
#define CP_WAIT(n)  asm volatile("cp.async.wait_group %0;" :: "n"(n) : "memory")

#define MMA_F16(c, a0, a1, a2, a3, b0, b1) \
    asm volatile("mma.sync.aligned.m16n8k16.row.col.f32.f16.f16.f32 " \
                 "{%0,%1,%2,%3}, {%4,%5,%6,%7}, {%8,%9}, {%0,%1,%2,%3};" \
                 : "+f"((c)[0]), "+f"((c)[1]), "+f"((c)[2]), "+f"((c)[3]) \
                 : "r"(a0), "r"(a1), "r"(a2), "r"(a3), "r"(b0), "r"(b1))

// (1/sqrt(128)) * log2(e) folded into Q at xpos time
#define QSCALE (0.08838834764831845f * 1.4426950408889634f)

// ---------------------------------------------------------------------------
// fused fp32 -> fp16 conversion for activations + the 4 weights
// ---------------------------------------------------------------------------
__global__ __launch_bounds__(256)
void cvt_f16_all(const float* __restrict__ act,
                 const float* __restrict__ wq, const float* __restrict__ wk,
                 const float* __restrict__ wv, const float* __restrict__ wo) {
    int blk = blockIdx.x;
    const float* src;
    __half* dst;
    size_t base;
    if (blk < 4096) {
        src = act; dst = g_acth; base = (size_t)blk * 2048;
    } else {
        int wb = blk - 4096;
        int w = wb >> 11;
        int bb = wb & 2047;
        base = (size_t)bb * 2048;
        if (w == 0)      { src = wq; dst = g_wqh; }
        else if (w == 1) { src = wk; dst = g_wkh; }
        else if (w == 2) { src = wv; dst = g_wvh; }
        else             { src = wo; dst = g_woh; }
    }
    size_t idx = base + (size_t)threadIdx.x * 8;
    float4 v0 = *(const float4*)(src + idx);
    float4 v1 = *(const float4*)(src + idx + 4);
    uint4 o;
    o.x = h2u(__floats2half2_rn(v0.x, v0.y));
    o.y = h2u(__floats2half2_rn(v0.z, v0.w));
    o.z = h2u(__floats2half2_rn(v1.x, v1.y));
    o.w = h2u(__floats2half2_rn(v1.z, v1.w));
    *(uint4*)(dst + idx) = o;
}

// ---------------------------------------------------------------------------
// fp16 mma.sync GEMM (NT) body (validated in R6).
// ---------------------------------------------------------------------------
#define BM 128
#define BN 128
#define BKH 32
#define SROW 20
#define TILE_U (128 * SROW)
#define STAGE_U (2 * TILE_U)
#define STAGE_B (STAGE_U * 4)
#define GM_STAGES 4
#define GM_SMEM (GM_STAGES * STAGE_B)
#define NK (EMB / BKH)

__device__ __forceinline__
void gemm_body(const __half* __restrict__ A, const __half* __restrict__ B,
               float* __restrict__ C, uint32_t* smu) {
    const uint32_t sb = smem_u32(smu);
    const int tid = threadIdx.x;
    const int wid = tid >> 5;
    const int lane = tid & 31;
    const int gid = lane >> 2;
    const int tig = lane & 3;
    const int wm = wid >> 2;
    const int wn = wid & 3;
    const int bm = blockIdx.y * BM;
    const int bn = blockIdx.x * BN;

    float acc[4][4][4];
#pragma unroll
    for (int mi = 0; mi < 4; mi++)
#pragma unroll
        for (int ni = 0; ni < 4; ni++)
#pragma unroll
            for (int q = 0; q < 4; q++) acc[mi][ni][q] = 0.0f;

    auto issue_stage = [&](int kt, int stage) {
        const uint32_t sbase = sb + stage * STAGE_B;
#pragma unroll
        for (int c = 0; c < 2; c++) {
            int id = tid + c * 256;
            int row = id >> 2;
            int cg = id & 3;
            uint32_t soff = (uint32_t)(row * SROW + cg * 4) * 4u;
            const __half* gaA = A + (size_t)(bm + row) * EMB + kt * BKH + cg * 8;
            const __half* gaB = B + (size_t)(bn + row) * EMB + kt * BKH + cg * 8;
            CP_ASYNC16(sbase + soff, gaA);
            CP_ASYNC16(sbase + TILE_U * 4 + soff, gaB);
        }
        CP_COMMIT();
    };

    issue_stage(0, 0);
    issue_stage(1, 1);
    issue_stage(2, 2);

    for (int kt = 0; kt < NK; kt++) {
        const int s = kt & 3;
        if (kt + 3 < NK) { CP_WAIT(2); } else if (kt + 2 < NK) { CP_WAIT(1); } else { CP_WAIT(0); }
        __syncthreads();

        const uint32_t* As = smu + s * STAGE_U;
        const uint32_t* Bs = As + TILE_U;
        const int am0 = wm * 64;
        const int bn0 = wn * 32;

#pragma unroll
        for (int ks = 0; ks < 2; ks++) {
            const int k0 = ks * 8;
            uint32_t a[4][4];
#pragma unroll
            for (int mi = 0; mi < 4; mi++) {
                const int r0 = am0 + mi * 16 + gid;
                a[mi][0] = As[r0 * SROW + k0 + tig];
                a[mi][1] = As[(r0 + 8) * SROW + k0 + tig];
                a[mi][2] = As[r0 * SROW + k0 + tig + 4];
                a[mi][3] = As[(r0 + 8) * SROW + k0 + tig + 4];
            }
            uint32_t b[4][2];
#pragma unroll
            for (int ni = 0; ni < 4; ni++) {
                const int n0 = bn0 + ni * 8 + gid;
                b[ni][0] = Bs[n0 * SROW + k0 + tig];
                b[ni][1] = Bs[n0 * SROW + k0 + tig + 4];
            }
#pragma unroll
            for (int mi = 0; mi < 4; mi++)
#pragma unroll
                for (int ni = 0; ni < 4; ni++)
                    MMA_F16(acc[mi][ni], a[mi][0], a[mi][1], a[mi][2], a[mi][3],
                            b[ni][0], b[ni][1]);
        }
        if (kt + 3 < NK) issue_stage(kt + 3, (kt + 3) & 3);
    }

#pragma unroll
    for (int mi = 0; mi < 4; mi++) {
        const int r0 = bm + wm * 64 + mi * 16 + gid;
#pragma unroll
        for (int ni = 0; ni < 4; ni++) {
            const int c0 = bn + wn * 32 + ni * 8 + tig * 2;
            float2 w0; w0.x = acc[mi][ni][0]; w0.y = acc[mi][ni][1];
            float2 w1; w1.x = acc[mi][ni][2]; w1.y = acc[mi][ni][3];
            *(float2*)(C + (size_t)r0 * EMB + c0) = w0;
            *(float2*)(C + (size_t)(r0 + 8) * EMB + c0) = w1;
        }
    }
}

__global__ __launch_bounds__(256, 2)
void gemm_f16(const __half* __restrict__ A, const __half* __restrict__ B,
              float* __restrict__ C) {
    extern __shared__ uint32_t smu[];
    gemm_body(A, B, C, smu);
}

// Q and K GEMMs merged into one launch via blockIdx.z
__global__ __launch_bounds__(256, 2)
void gemm_qk(const __half* __restrict__ A,
             const __half* __restrict__ Bq, const __half* __restrict__ Bk,
             float* __restrict__ Cq, float* __restrict__ Ck) {
    extern __shared__ uint32_t smu[];
    if (blockIdx.z == 0) gemm_body(A, Bq, Cq, smu);
    else                 gemm_body(A, Bk, Ck, smu);
}

// ---------------------------------------------------------------------------
// xpos rotary: reads fp32 q/k, writes fp16 qh (scaled by QSCALE) and kh.
// ---------------------------------------------------------------------------
__global__ __launch_bounds__(256)
void xpos_kernel() {
    int idx = blockIdx.x * 256 + threadIdx.x;
    int pair = idx & 63;
    int h = (idx >> 6) & (HEADS - 1);
    int bs = idx >> 10;
    int s = bs & (SEQ - 1);

    float seq = (float)(s - SEQ / 2) * (1.0f / 512.0f);
    float dr = 2.0f * (float)(pair + 1);
    float theta = powf(1.0e-4f, dr * (1.0f / 128.0f));
    float zeta = (dr * (1.0f / 64.0f) + 51.2f) * (1.0f / 52.2f);
    float ang = seq * theta;
    float c = cosf(ang);
    float sn = sinf(ang);
    float t = powf(zeta, seq);
    float it = 1.0f / t;

    size_t base = (size_t)bs * EMB + h * HDIM + pair * 2;
    float2 qv = *(float2*)(g_q + base);
    float2 kv = *(float2*)(g_k + base);
    float qx = (qv.x * c - qv.y * sn) * t * QSCALE;
    float qy = (qv.y * c + qv.x * sn) * t * QSCALE;
    float kx = (kv.x * c - kv.y * sn) * it;
    float ky = (kv.y * c + kv.x * sn) * it;
    *(__half2*)(g_qh + base) = __floats2half2_rn(qx, qy);
    *(__half2*)(g_kh + base) = __floats2half2_rn(kx, ky);
}

// ---------------------------------------------------------------------------
// V transpose: g_v fp32 [b][s][h*128+d] -> g_vth fp16 [bh][d][s]
// 64x64 tiles, 256 threads.
// ---------------------------------------------------------------------------
__global__ __launch_bounds__(256)
void vtrans_kernel() {
    __shared__ float tile[64][65];
    int bidx = blockIdx.x;
    int bh = bidx >> 6;
    int rest = bidx & 63;
    int s0 = (rest >> 1) * 64;
    int d0 = (rest & 1) * 64;
    int b = bh >> 4, h = bh & 15;
    int tid = threadIdx.x;
#pragma unroll
    for (int i = 0; i < 16; i++) {
        int id = tid + i * 256;
        int r = id >> 6, c = id & 63;
        tile[r][c] = g_v[((size_t)b * SEQ + s0 + r) * EMB + h * HDIM + d0 + c];
    }
    __syncthreads();
#pragma unroll
    for (int i = 0; i < 16; i++) {
        int id = tid + i * 256;
        int r = id >> 6, c = id & 63;   // r = dim-local, c = key-local
        g_vth[((size_t)bh * HDIM + d0 + r) * SEQ + s0 + c] =
            __float2half_rn(tile[c][r]);
    }
}

// ---------------------------------------------------------------------------
// FlashAttention-2 style causal attention, fp16 mma.sync, fp32 softmax/accum.
// CTA = 128 threads (4 warps) = 64 query rows; warp owns 16 rows.
// K tile [64 keys][128 dims] fp16 smem (rows padded to 136 halves);
// Vt tile [128 dims][64 keys] fp16 smem (rows padded to 72 halves).
// grid = 1024 CTAs (32 bh x 32 qtiles), longest qtiles first.
// ---------------------------------------------------------------------------
__global__ __launch_bounds__(128, 2)
void attn_kernel() {
    __shared__ __half Ks[64 * 136];
    __shared__ __half Vts[128 * 72];
    uint32_t* Ksu = (uint32_t*)Ks;
    uint32_t* Vtu = (uint32_t*)Vts;

    const int bid = blockIdx.x;
    const int bh = bid & 31;
    const int qt = 31 - (bid >> 5);   // longest first
    const int b = bh >> 4;
    const int h = bh & 15;
    const int q0 = qt * 64;

    const int tid = threadIdx.x;
    const int wid = tid >> 5;
    const int lane = tid & 31;
    const int gid = lane >> 2;
    const int tig = lane & 3;

    const int row0 = q0 + wid * 16 + gid;
    const int row1 = row0 + 8;

    // Q fragments (8 ksteps over dim-128, 4 regs each)
    uint32_t aQ[8][4];
    {
        const __half* q0p = g_qh + ((size_t)b * SEQ + row0) * EMB + h * HDIM;
        const __half* q1p = q0p + 8 * EMB;
#pragma unroll
        for (int t = 0; t < 8; t++) {
            aQ[t][0] = *(const uint32_t*)(q0p + t * 16 + 2 * tig);
            aQ[t][1] = *(const uint32_t*)(q1p + t * 16 + 2 * tig);
            aQ[t][2] = *(const uint32_t*)(q0p + t * 16 + 8 + 2 * tig);
            aQ[t][3] = *(const uint32_t*)(q1p + t * 16 + 8 + 2 * tig);
        }
    }

    float O[16][4];
#pragma unroll
    for (int n = 0; n < 16; n++) { O[n][0] = O[n][1] = O[n][2] = O[n][3] = 0.f; }
    float m0 = -1e30f, m1 = -1e30f, l0 = 0.f, l1 = 0.f;

    const __half* kg = g_kh + (size_t)b * SEQ * EMB + h * HDIM;
    const __half* vtg = g_vth + (size_t)bh * HDIM * SEQ;
    const uint32_t ks_b = smem_u32(Ks);
    const uint32_t vt_b = smem_u32(Vts);

    for (int kt = 0; kt <= qt; kt++) {
        __syncthreads();
        // K tile: 64 rows x 16 chunks (16B each)
#pragma unroll
        for (int i = 0; i < 8; i++) {
            int id = tid + i * 128;
            int row = id >> 4, ch = id & 15;
            CP_ASYNC16(ks_b + (uint32_t)(row * 136 + ch * 8) * 2,
                       kg + (size_t)(kt * 64 + row) * EMB + ch * 8);
        }
        // Vt tile: 128 rows x 8 chunks
#pragma unroll
        for (int i = 0; i < 8; i++) {
            int id = tid + i * 128;
            int row = id >> 3, ch = id & 7;
            CP_ASYNC16(vt_b + (uint32_t)(row * 72 + ch * 8) * 2,
                       vtg + (size_t)row * SEQ + kt * 64 + ch * 8);
        }
        CP_COMMIT(); CP_WAIT(0);
        __syncthreads();

        // S = Q K^T : 8 n-tiles (keys) x fp32 C fragments
        float s[8][4];
#pragma unroll
        for (int n = 0; n < 8; n++) s[n][0] = s[n][1] = s[n][2] = s[n][3] = 0.f;
#pragma unroll
        for (int t = 0; t < 8; t++) {
#pragma unroll
            for (int n = 0; n < 8; n++) {
                uint32_t kb0 = Ksu[(n * 8 + gid) * 68 + t * 8 + tig];
                uint32_t kb1 = Ksu[(n * 8 + gid) * 68 + t * 8 + tig + 4];
                MMA_F16(s[n], aQ[t][0], aQ[t][1], aQ[t][2], aQ[t][3], kb0, kb1);
            }
        }

        // causal mask (diagonal tile only)
        if (kt == qt) {
#pragma unroll
            for (int n = 0; n < 8; n++) {
                int col = kt * 64 + n * 8 + 2 * tig;
                if (col > row0)     s[n][0] = -1e30f;
                if (col + 1 > row0) s[n][1] = -1e30f;
                if (col > row1)     s[n][2] = -1e30f;
                if (col + 1 > row1) s[n][3] = -1e30f;
            }
        }

        // online softmax (log2 domain; Q pre-scaled)
        float rm0 = -1e30f, rm1 = -1e30f;
#pragma unroll
        for (int n = 0; n < 8; n++) {
            rm0 = fmaxf(rm0, fmaxf(s[n][0], s[n][1]));
            rm1 = fmaxf(rm1, fmaxf(s[n][2], s[n][3]));
        }
        rm0 = fmaxf(rm0, __shfl_xor_sync(0xffffffffu, rm0, 1));
        rm0 = fmaxf(rm0, __shfl_xor_sync(0xffffffffu, rm0, 2));
        rm1 = fmaxf(rm1, __shfl_xor_sync(0xffffffffu, rm1, 1));
        rm1 = fmaxf(rm1, __shfl_xor_sync(0xffffffffu, rm1, 2));
        float mn0 = fmaxf(m0, rm0), mn1 = fmaxf(m1, rm1);
        float cf0 = ex2(m0 - mn0), cf1 = ex2(m1 - mn1);
        m0 = mn0; m1 = mn1;

        float rs0 = 0.f, rs1 = 0.f;
        uint32_t aP[4][4];
#pragma unroll
        for (int t = 0; t < 4; t++) {
            float p00 = ex2(s[2 * t][0] - mn0),     p01 = ex2(s[2 * t][1] - mn0);
            float p02 = ex2(s[2 * t][2] - mn1),     p03 = ex2(s[2 * t][3] - mn1);
            float p10 = ex2(s[2 * t + 1][0] - mn0), p11 = ex2(s[2 * t + 1][1] - mn0);
            float p12 = ex2(s[2 * t + 1][2] - mn1), p13 = ex2(s[2 * t + 1][3] - mn1);
            rs0 += (p00 + p01) + (p10 + p11);
            rs1 += (p02 + p03) + (p12 + p13);
            aP[t][0] = h2u(__floats2half2_rn(p00, p01));
            aP[t][1] = h2u(__floats2half2_rn(p02, p03));
            aP[t][2] = h2u(__floats2half2_rn(p10, p11));
            aP[t][3] = h2u(__floats2half2_rn(p12, p13));
        }
        l0 = l0 * cf0 + rs0;     // lane-partial; reduced at end
        l1 = l1 * cf1 + rs1;

#pragma unroll
        for (int n = 0; n < 16; n++) {
            O[n][0] *= cf0; O[n][1] *= cf0; O[n][2] *= cf1; O[n][3] *= cf1;
        }

        // O += P V : 16 n-tiles (dims) x 4 ksteps (keys)
#pragma unroll
        for (int t = 0; t < 4; t++) {
#pragma unroll
            for (int n = 0; n < 16; n++) {
                uint32_t vb0 = Vtu[(n * 8 + gid) * 36 + t * 8 + tig];
                uint32_t vb1 = Vtu[(n * 8 + gid) * 36 + t * 8 + tig + 4];
                MMA_F16(O[n], aP[t][0], aP[t][1], aP[t][2], aP[t][3], vb0, vb1);
            }
        }
    }

    l0 += __shfl_xor_sync(0xffffffffu, l0, 1);
    l0 += __shfl_xor_sync(0xffffffffu, l0, 2);
    l1 += __shfl_xor_sync(0xffffffffu, l1, 1);
    l1 += __shfl_xor_sync(0xffffffffu, l1, 2);
    float inv0 = 1.0f / l0, inv1 = 1.0f / l1;

    __half* o0 = g_atth + ((size_t)b * SEQ + row0) * EMB + h * HDIM;
    __half* o1 = o0 + 8 * EMB;
#pragma unroll
    for (int n = 0; n < 16; n++) {
        *(uint32_t*)(o0 + n * 8 + 2 * tig) =
            h2u(__floats2half2_rn(O[n][0] * inv0, O[n][1] * inv0));
        *(uint32_t*)(o1 + n * 8 + 2 * tig) =
            h2u(__floats2half2_rn(O[n][2] * inv1, O[n][3] * inv1));
    }
}

// ---------------------------------------------------------------------------
// Launch. Order: cvt, QK-gemm, xpos, V-gemm, vtrans, attn (6th: ncu), O-gemm.
// ---------------------------------------------------------------------------
extern "C" void kernel_launch(void* const* d_in, const int* in_sizes, int n_in,
                              void* d_out, int out_size) {
    const float* act = (const float*)d_in[0];
    const float* Wq  = (const float*)d_in[1];
    const float* Wk  = (const float*)d_in[2];
    const float* Wv  = (const float*)d_in[3];
    const float* Wo  = (const float*)d_in[4];
    float* out = (float*)d_out;

    float *qp, *kp, *vp;
    __half *acth, *atth, *wqh, *wkh, *wvh, *woh;
    cudaGetSymbolAddress((void**)&qp, g_q);
    cudaGetSymbolAddress((void**)&kp, g_k);
    cudaGetSymbolAddress((void**)&vp, g_v);
    cudaGetSymbolAddress((void**)&acth, g_acth);
    cudaGetSymbolAddress((void**)&atth, g_atth);
    cudaGetSymbolAddress((void**)&wqh, g_wqh);
    cudaGetSymbolAddress((void**)&wkh, g_wkh);
    cudaGetSymbolAddress((void**)&wvh, g_wvh);
    cudaGetSymbolAddress((void**)&woh, g_woh);

    cudaFuncSetAttribute(gemm_f16, cudaFuncAttributeMaxDynamicSharedMemorySize, GM_SMEM);
    cudaFuncSetAttribute(gemm_qk, cudaFuncAttributeMaxDynamicSharedMemorySize, GM_SMEM);

    dim3 ggrid(EMB / BN, BATCH * SEQ / BM);          // (16, 32)
    dim3 qkgrid(EMB / BN, BATCH * SEQ / BM, 2);      // (16, 32, 2)

    // 1: conversions
    cvt_f16_all<<<4096 + 4 * 2048, 256>>>(act, Wq, Wk, Wv, Wo);
    // 2: Q and K GEMMs (one launch)
    gemm_qk<<<qkgrid, 256, GM_SMEM>>>(acth, wqh, wkh, qp, kp);
    // 3: xpos -> fp16 qh/kh
    int nrot = BATCH * SEQ * HEADS * 64;
    xpos_kernel<<<nrot / 256, 256>>>();
    // 4: V GEMM
    gemm_f16<<<ggrid, 256, GM_SMEM>>>(acth, wvh, vp);
    // 5: V transpose -> fp16 vth
    vtrans_kernel<<<32 * 64, 256>>>();
    // 6: attention (ncu capture target)
    attn_kernel<<<1024, 128>>>();
    // 7: output GEMM
    gemm_f16<<<ggrid, 256, GM_SMEM>>>(atth, woh, out);
}

// round 9
// speedup vs baseline: 15.0877x; 1.1637x over previous
#include <cuda_runtime.h>
#include <cuda_fp16.h>
#include <math.h>
#include <stdint.h>

// Problem constants
#define BATCH 2
#define SEQ   2048
#define EMB   2048
#define HEADS 16
#define HDIM  128

// Scratch buffers (allocation-free rule: __device__ globals)
__device__ __half g_acth[BATCH * SEQ * EMB];  // fp16 activations
__device__ __half g_atth[BATCH * SEQ * EMB];  // fp16 attention output
__device__ __half g_qh[BATCH * SEQ * EMB];    // fp16 rotated+scaled Q
__device__ __half g_kh[BATCH * SEQ * EMB];    // fp16 rotated K
__device__ __half g_vh[BATCH * SEQ * EMB];    // fp16 V (row-major)
__device__ __half g_vth[32 * HDIM * SEQ];     // fp16 V transposed per (b,h)
__device__ __half g_wqh[EMB * EMB];
__device__ __half g_wkh[EMB * EMB];
__device__ __half g_wvh[EMB * EMB];
__device__ __half g_woh[EMB * EMB];

// ---------------------------------------------------------------------------
// helpers
// ---------------------------------------------------------------------------
__device__ __forceinline__ uint32_t smem_u32(const void* p) {
    uint32_t a;
    asm("{ .reg .u64 t; cvta.to.shared.u64 t, %1; cvt.u32.u64 %0, t; }"
        : "=r"(a) : "l"(p));
    return a;
}

__device__ __forceinline__ float ex2(float x) {
    float r;
    asm("ex2.approx.ftz.f32 %0, %1;" : "=f"(r) : "f"(x));
    return r;
}

__device__ __forceinline__ uint32_t h2u(__half2 h) {
    return *reinterpret_cast<uint32_t*>(&h);
}

#define CP_ASYNC16(saddr, gaddr) \
    asm volatile("cp.async.ca.shared.global [%0], [%1], 16;" \
                 :: "r"(saddr), "l"(gaddr) : "memory")
#define CP_COMMIT() asm volatile("cp.async.commit_group;" ::: "memory")
#define CP_WAIT(n)  asm volatile("cp.async.wait_group %0;" :: "n"(n) : "memory")

#define MMA_F16(c, a0, a1, a2, a3, b0, b1) \
    asm volatile("mma.sync.aligned.m16n8k16.row.col.f32.f16.f16.f32 " \
                 "{%0,%1,%2,%3}, {%4,%5,%6,%7}, {%8,%9}, {%0,%1,%2,%3};" \
                 : "+f"((c)[0]), "+f"((c)[1]), "+f"((c)[2]), "+f"((c)[3]) \
                 : "r"(a0), "r"(a1), "r"(a2), "r"(a3), "r"(b0), "r"(b1))

#define LDSM4(r0, r1, r2, r3, a) \
    asm volatile("ldmatrix.sync.aligned.m8n8.x4.shared.b16 {%0,%1,%2,%3}, [%4];" \
                 : "=r"(r0), "=r"(r1), "=r"(r2), "=r"(r3) : "r"(a))

// (1/sqrt(128)) * log2(e) folded into Q
#define QSCALE (0.08838834764831845f * 1.4426950408889634f)

// ---------------------------------------------------------------------------
// fused fp32 -> fp16 conversion for activations + the 4 weights
// ---------------------------------------------------------------------------
__global__ __launch_bounds__(256)
void cvt_f16_all(const float* __restrict__ act,
                 const float* __restrict__ wq, const float* __restrict__ wk,
                 const float* __restrict__ wv, const float* __restrict__ wo) {
    int blk = blockIdx.x;
    const float* src;
    __half* dst;
    size_t base;
    if (blk < 4096) {
        src = act; dst = g_acth; base = (size_t)blk * 2048;
    } else {
        int wb = blk - 4096;
        int w = wb >> 11;
        int bb = wb & 2047;
        base = (size_t)bb * 2048;
        if (w == 0)      { src = wq; dst = g_wqh; }
        else if (w == 1) { src = wk; dst = g_wkh; }
        else if (w == 2) { src = wv; dst = g_wvh; }
        else             { src = wo; dst = g_woh; }
    }
    size_t idx = base + (size_t)threadIdx.x * 8;
    float4 v0 = *(const float4*)(src + idx);
    float4 v1 = *(const float4*)(src + idx + 4);
    uint4 o;
    o.x = h2u(__floats2half2_rn(v0.x, v0.y));
    o.y = h2u(__floats2half2_rn(v0.z, v0.w));
    o.z = h2u(__floats2half2_rn(v1.x, v1.y));
    o.w = h2u(__floats2half2_rn(v1.z, v1.w));
    *(uint4*)(dst + idx) = o;
}

// ---------------------------------------------------------------------------
// fp16 mma.sync GEMM (NT) with ldmatrix fragment loads.
// MODE 0: fp32 C;  1: fp16 C;  2: xpos-Q fp16;  3: xpos-K fp16.
// ---------------------------------------------------------------------------
#define BM 128
#define BN 128
#define BKH 32
#define SROW 20
#define TILE_U (128 * SROW)
#define STAGE_U (2 * TILE_U)
#define STAGE_B (STAGE_U * 4)
#define GM_STAGES 4
#define GM_SMEM (GM_STAGES * STAGE_B)
#define NK (EMB / BKH)

template<int MODE>
__device__ __forceinline__
void gemm_body(const __half* __restrict__ A, const __half* __restrict__ B,
               void* __restrict__ Cv, uint32_t* smu) {
    const uint32_t sb = smem_u32(smu);
    const int tid = threadIdx.x;
    const int wid = tid >> 5;
    const int lane = tid & 31;
    const int gid = lane >> 2;
    const int tig = lane & 3;
    const int wm = wid >> 2;
    const int wn = wid & 3;
    const int bm = blockIdx.y * BM;
    const int bn = blockIdx.x * BN;

    // ldmatrix per-lane offsets (u32 index into tile)
    const int l7 = lane & 7;
    const int rA = ((lane >> 3) & 1) * 8;   // A: matrices 1,3 -> +8 rows
    const int kA = ((lane >> 4) & 1) * 4;   // A: matrices 2,3 -> k-half 1
    const int rB = ((lane >> 4) & 1) * 8;   // B: matrices 2,3 -> +8 rows
    const int kB = ((lane >> 3) & 1) * 4;   // B: matrices 1,3 -> k-half 1
    int aoff[4], boff[2];
#pragma unroll
    for (int mi = 0; mi < 4; mi++)
        aoff[mi] = (wm * 64 + mi * 16 + l7 + rA) * SROW + kA;
#pragma unroll
    for (int p = 0; p < 2; p++)
        boff[p] = (wn * 32 + p * 16 + l7 + rB) * SROW + kB;

    float acc[4][4][4];
#pragma unroll
    for (int mi = 0; mi < 4; mi++)
#pragma unroll
        for (int ni = 0; ni < 4; ni++)
#pragma unroll
            for (int q = 0; q < 4; q++) acc[mi][ni][q] = 0.0f;

    auto issue_stage = [&](int kt, int stage) {
        const uint32_t sbase = sb + stage * STAGE_B;
#pragma unroll
        for (int c = 0; c < 2; c++) {
            int id = tid + c * 256;
            int row = id >> 2;
            int cg = id & 3;
            uint32_t soff = (uint32_t)(row * SROW + cg * 4) * 4u;
            const __half* gaA = A + (size_t)(bm + row) * EMB + kt * BKH + cg * 8;
            const __half* gaB = B + (size_t)(bn + row) * EMB + kt * BKH + cg * 8;
            CP_ASYNC16(sbase + soff, gaA);
            CP_ASYNC16(sbase + TILE_U * 4 + soff, gaB);
        }
        CP_COMMIT();
    };

    issue_stage(0, 0);
    issue_stage(1, 1);
    issue_stage(2, 2);

    for (int kt = 0; kt < NK; kt++) {
        const int s = kt & 3;
        if (kt + 3 < NK) { CP_WAIT(2); } else if (kt + 2 < NK) { CP_WAIT(1); } else { CP_WAIT(0); }
        __syncthreads();

        const uint32_t aB = sb + s * STAGE_B;
        const uint32_t bB = aB + TILE_U * 4;

#pragma unroll
        for (int ks = 0; ks < 2; ks++) {
            const int k0 = ks * 8;
            uint32_t a[4][4];
#pragma unroll
            for (int mi = 0; mi < 4; mi++)
                LDSM4(a[mi][0], a[mi][1], a[mi][2], a[mi][3],
                      aB + (uint32_t)(aoff[mi] + k0) * 4u);
            uint32_t bb[2][4];
#pragma unroll
            for (int p = 0; p < 2; p++)
                LDSM4(bb[p][0], bb[p][1], bb[p][2], bb[p][3],
                      bB + (uint32_t)(boff[p] + k0) * 4u);
#pragma unroll
            for (int mi = 0; mi < 4; mi++)
#pragma unroll
                for (int p = 0; p < 2; p++) {
                    MMA_F16(acc[mi][2 * p], a[mi][0], a[mi][1], a[mi][2], a[mi][3],
                            bb[p][0], bb[p][1]);
                    MMA_F16(acc[mi][2 * p + 1], a[mi][0], a[mi][1], a[mi][2], a[mi][3],
                            bb[p][2], bb[p][3]);
                }
        }
        if (kt + 3 < NK) issue_stage(kt + 3, (kt + 3) & 3);
    }

    // epilogue
#pragma unroll
    for (int mi = 0; mi < 4; mi++) {
        const int r0 = bm + wm * 64 + mi * 16 + gid;
        const int r1 = r0 + 8;
#pragma unroll
        for (int ni = 0; ni < 4; ni++) {
            const int c0 = bn + wn * 32 + ni * 8 + tig * 2;
            if (MODE == 0) {
                float* C = (float*)Cv;
                float2 w0; w0.x = acc[mi][ni][0]; w0.y = acc[mi][ni][1];
                float2 w1; w1.x = acc[mi][ni][2]; w1.y = acc[mi][ni][3];
                *(float2*)(C + (size_t)r0 * EMB + c0) = w0;
                *(float2*)(C + (size_t)r1 * EMB + c0) = w1;
            } else if (MODE == 1) {
                __half* C = (__half*)Cv;
                *(uint32_t*)(C + (size_t)r0 * EMB + c0) =
                    h2u(__floats2half2_rn(acc[mi][ni][0], acc[mi][ni][1]));
                *(uint32_t*)(C + (size_t)r1 * EMB + c0) =
                    h2u(__floats2half2_rn(acc[mi][ni][2], acc[mi][ni][3]));
            } else {
                // xpos rotary fused: col pair (c0, c0+1), dr = (c0&127)+2
                __half* C = (__half*)Cv;
                float dr = (float)((c0 & 127) + 2);
                float theta = ex2(-0.1038102531f * dr);           // (1e-4)^(dr/128)
                float lz = __log2f((dr * 0.015625f + 51.2f) * (1.0f / 52.2f));
                float seq0 = (float)((r0 & (SEQ - 1)) - 1024) * (1.0f / 512.0f);
                float seq1 = (float)((r1 & (SEQ - 1)) - 1024) * (1.0f / 512.0f);
                float c0f = __cosf(seq0 * theta), s0f = __sinf(seq0 * theta);
                float c1f = __cosf(seq1 * theta), s1f = __sinf(seq1 * theta);
                float t0, t1;
                if (MODE == 2) { t0 = ex2(seq0 * lz) * QSCALE; t1 = ex2(seq1 * lz) * QSCALE; }
                else           { t0 = ex2(-seq0 * lz);         t1 = ex2(-seq1 * lz); }
                float x0 = acc[mi][ni][0], y0 = acc[mi][ni][1];
                float x1 = acc[mi][ni][2], y1 = acc[mi][ni][3];
                float ox0 = (x0 * c0f - y0 * s0f) * t0;
                float oy0 = (y0 * c0f + x0 * s0f) * t0;
                float ox1 = (x1 * c1f - y1 * s1f) * t1;
                float oy1 = (y1 * c1f + x1 * s1f) * t1;
                *(uint32_t*)(C + (size_t)r0 * EMB + c0) = h2u(__floats2half2_rn(ox0, oy0));
                *(uint32_t*)(C + (size_t)r1 * EMB + c0) = h2u(__floats2half2_rn(ox1, oy1));
            }
        }
    }
}

__global__ __launch_bounds__(256, 2)
void gemm_out(const __half* __restrict__ A, const __half* __restrict__ B,
              float* __restrict__ C) {
    extern __shared__ uint32_t smu[];
    gemm_body<0>(A, B, (void*)C, smu);
}

__global__ __launch_bounds__(256, 2)
void gemm_v(const __half* __restrict__ A, const __half* __restrict__ B,
            __half* __restrict__ C) {
    extern __shared__ uint32_t smu[];
    gemm_body<1>(A, B, (void*)C, smu);
}

__global__ __launch_bounds__(256, 2)
void gemm_qk(const __half* __restrict__ A,
             const __half* __restrict__ Bq, const __half* __restrict__ Bk,
             __half* __restrict__ Cq, __half* __restrict__ Ck) {
    extern __shared__ uint32_t smu[];
    if (blockIdx.z == 0) gemm_body<2>(A, Bq, (void*)Cq, smu);
    else                 gemm_body<3>(A, Bk, (void*)Ck, smu);
}

// ---------------------------------------------------------------------------
// V transpose: g_vh fp16 [b][s][h*128+d] -> g_vth fp16 [bh][d][s]
// ---------------------------------------------------------------------------
__global__ __launch_bounds__(256)
void vtrans_kernel() {
    __shared__ float tile[64][65];
    int bidx = blockIdx.x;
    int bh = bidx >> 6;
    int rest = bidx & 63;
    int s0 = (rest >> 1) * 64;
    int d0 = (rest & 1) * 64;
    int b = bh >> 4, h = bh & 15;
    int tid = threadIdx.x;
#pragma unroll
    for (int i = 0; i < 16; i++) {
        int id = tid + i * 256;
        int r = id >> 6, c = id & 63;
        tile[r][c] = __half2float(
            g_vh[((size_t)b * SEQ + s0 + r) * EMB + h * HDIM + d0 + c]);
    }
    __syncthreads();
#pragma unroll
    for (int i = 0; i < 16; i++) {
        int id = tid + i * 256;
        int r = id >> 6, c = id & 63;
        g_vth[((size_t)bh * HDIM + d0 + r) * SEQ + s0 + c] =
            __float2half_rn(tile[c][r]);
    }
}

// ---------------------------------------------------------------------------
// FlashAttention-2 style causal attention (validated in R8, unchanged).
// ---------------------------------------------------------------------------
__global__ __launch_bounds__(128, 2)
void attn_kernel() {
    __shared__ __half Ks[64 * 136];
    __shared__ __half Vts[128 * 72];
    uint32_t* Ksu = (uint32_t*)Ks;
    uint32_t* Vtu = (uint32_t*)Vts;

    const int bid = blockIdx.x;
    const int bh = bid & 31;
    const int qt = 31 - (bid >> 5);
    const int b = bh >> 4;
    const int h = bh & 15;
    const int q0 = qt * 64;

    const int tid = threadIdx.x;
    const int wid = tid >> 5;
    const int lane = tid & 31;
    const int gid = lane >> 2;
    const int tig = lane & 3;

    const int row0 = q0 + wid * 16 + gid;
    const int row1 = row0 + 8;

    uint32_t aQ[8][4];
    {
        const __half* q0p = g_qh + ((size_t)b * SEQ + row0) * EMB + h * HDIM;
        const __half* q1p = q0p + 8 * EMB;
#pragma unroll
        for (int t = 0; t < 8; t++) {
            aQ[t][0] = *(const uint32_t*)(q0p + t * 16 + 2 * tig);
            aQ[t][1] = *(const uint32_t*)(q1p + t * 16 + 2 * tig);
            aQ[t][2] = *(const uint32_t*)(q0p + t * 16 + 8 + 2 * tig);
            aQ[t][3] = *(const uint32_t*)(q1p + t * 16 + 8 + 2 * tig);
        }
    }

    float O[16][4];
#pragma unroll
    for (int n = 0; n < 16; n++) { O[n][0] = O[n][1] = O[n][2] = O[n][3] = 0.f; }
    float m0 = -1e30f, m1 = -1e30f, l0 = 0.f, l1 = 0.f;

    const __half* kg = g_kh + (size_t)b * SEQ * EMB + h * HDIM;
    const __half* vtg = g_vth + (size_t)bh * HDIM * SEQ;
    const uint32_t ks_b = smem_u32(Ks);
    const uint32_t vt_b = smem_u32(Vts);

    for (int kt = 0; kt <= qt; kt++) {
        __syncthreads();
#pragma unroll
        for (int i = 0; i < 8; i++) {
            int id = tid + i * 128;
            int row = id >> 4, ch = id & 15;
            CP_ASYNC16(ks_b + (uint32_t)(row * 136 + ch * 8) * 2,
                       kg + (size_t)(kt * 64 + row) * EMB + ch * 8);
        }
#pragma unroll
        for (int i = 0; i < 8; i++) {
            int id = tid + i * 128;
            int row = id >> 3, ch = id & 7;
            CP_ASYNC16(vt_b + (uint32_t)(row * 72 + ch * 8) * 2,
                       vtg + (size_t)row * SEQ + kt * 64 + ch * 8);
        }
        CP_COMMIT(); CP_WAIT(0);
        __syncthreads();

        float s[8][4];
#pragma unroll
        for (int n = 0; n < 8; n++) s[n][0] = s[n][1] = s[n][2] = s[n][3] = 0.f;
#pragma unroll
        for (int t = 0; t < 8; t++) {
#pragma unroll
            for (int n = 0; n < 8; n++) {
                uint32_t kb0 = Ksu[(n * 8 + gid) * 68 + t * 8 + tig];
                uint32_t kb1 = Ksu[(n * 8 + gid) * 68 + t * 8 + tig + 4];
                MMA_F16(s[n], aQ[t][0], aQ[t][1], aQ[t][2], aQ[t][3], kb0, kb1);
            }
        }

        if (kt == qt) {
#pragma unroll
            for (int n = 0; n < 8; n++) {
                int col = kt * 64 + n * 8 + 2 * tig;
                if (col > row0)     s[n][0] = -1e30f;
                if (col + 1 > row0) s[n][1] = -1e30f;
                if (col > row1)     s[n][2] = -1e30f;
                if (col + 1 > row1) s[n][3] = -1e30f;
            }
        }

        float rm0 = -1e30f, rm1 = -1e30f;
#pragma unroll
        for (int n = 0; n < 8; n++) {
            rm0 = fmaxf(rm0, fmaxf(s[n][0], s[n][1]));
            rm1 = fmaxf(rm1, fmaxf(s[n][2], s[n][3]));
        }
        rm0 = fmaxf(rm0, __shfl_xor_sync(0xffffffffu, rm0, 1));
        rm0 = fmaxf(rm0, __shfl_xor_sync(0xffffffffu, rm0, 2));
        rm1 = fmaxf(rm1, __shfl_xor_sync(0xffffffffu, rm1, 1));
        rm1 = fmaxf(rm1, __shfl_xor_sync(0xffffffffu, rm1, 2));
        float mn0 = fmaxf(m0, rm0), mn1 = fmaxf(m1, rm1);
        float cf0 = ex2(m0 - mn0), cf1 = ex2(m1 - mn1);
        m0 = mn0; m1 = mn1;

        float rs0 = 0.f, rs1 = 0.f;
        uint32_t aP[4][4];
#pragma unroll
        for (int t = 0; t < 4; t++) {
            float p00 = ex2(s[2 * t][0] - mn0),     p01 = ex2(s[2 * t][1] - mn0);
            float p02 = ex2(s[2 * t][2] - mn1),     p03 = ex2(s[2 * t][3] - mn1);
            float p10 = ex2(s[2 * t + 1][0] - mn0), p11 = ex2(s[2 * t + 1][1] - mn0);
            float p12 = ex2(s[2 * t + 1][2] - mn1), p13 = ex2(s[2 * t + 1][3] - mn1);
            rs0 += (p00 + p01) + (p10 + p11);
            rs1 += (p02 + p03) + (p12 + p13);
            aP[t][0] = h2u(__floats2half2_rn(p00, p01));
            aP[t][1] = h2u(__floats2half2_rn(p02, p03));
            aP[t][2] = h2u(__floats2half2_rn(p10, p11));
            aP[t][3] = h2u(__floats2half2_rn(p12, p13));
        }
        l0 = l0 * cf0 + rs0;
        l1 = l1 * cf1 + rs1;

#pragma unroll
        for (int n = 0; n < 16; n++) {
            O[n][0] *= cf0; O[n][1] *= cf0; O[n][2] *= cf1; O[n][3] *= cf1;
        }

#pragma unroll
        for (int t = 0; t < 4; t++) {
#pragma unroll
            for (int n = 0; n < 16; n++) {
                uint32_t vb0 = Vtu[(n * 8 + gid) * 36 + t * 8 + tig];
                uint32_t vb1 = Vtu[(n * 8 + gid) * 36 + t * 8 + tig + 4];
                MMA_F16(O[n], aP[t][0], aP[t][1], aP[t][2], aP[t][3], vb0, vb1);
            }
        }
    }

    l0 += __shfl_xor_sync(0xffffffffu, l0, 1);
    l0 += __shfl_xor_sync(0xffffffffu, l0, 2);
    l1 += __shfl_xor_sync(0xffffffffu, l1, 1);
    l1 += __shfl_xor_sync(0xffffffffu, l1, 2);
    float inv0 = 1.0f / l0, inv1 = 1.0f / l1;

    __half* o0 = g_atth + ((size_t)b * SEQ + row0) * EMB + h * HDIM;
    __half* o1 = o0 + 8 * EMB;
#pragma unroll
    for (int n = 0; n < 16; n++) {
        *(uint32_t*)(o0 + n * 8 + 2 * tig) =
            h2u(__floats2half2_rn(O[n][0] * inv0, O[n][1] * inv0));
        *(uint32_t*)(o1 + n * 8 + 2 * tig) =
            h2u(__floats2half2_rn(O[n][2] * inv1, O[n][3] * inv1));
    }
}

// ---------------------------------------------------------------------------
// Launch. Order: cvt, qk, v, vtrans, attn, out-gemm (6th: ncu target).
// ---------------------------------------------------------------------------
extern "C" void kernel_launch(void* const* d_in, const int* in_sizes, int n_in,
                              void* d_out, int out_size) {
    const float* act = (const float*)d_in[0];
    const float* Wq  = (const float*)d_in[1];
    const float* Wk  = (const float*)d_in[2];
    const float* Wv  = (const float*)d_in[3];
    const float* Wo  = (const float*)d_in[4];
    float* out = (float*)d_out;

    __half *acth, *atth, *qh, *kh, *vh, *wqh, *wkh, *wvh, *woh;
    cudaGetSymbolAddress((void**)&acth, g_acth);
    cudaGetSymbolAddress((void**)&atth, g_atth);
    cudaGetSymbolAddress((void**)&qh, g_qh);
    cudaGetSymbolAddress((void**)&kh, g_kh);
    cudaGetSymbolAddress((void**)&vh, g_vh);
    cudaGetSymbolAddress((void**)&wqh, g_wqh);
    cudaGetSymbolAddress((void**)&wkh, g_wkh);
    cudaGetSymbolAddress((void**)&wvh, g_wvh);
    cudaGetSymbolAddress((void**)&woh, g_woh);

    cudaFuncSetAttribute(gemm_out, cudaFuncAttributeMaxDynamicSharedMemorySize, GM_SMEM);
    cudaFuncSetAttribute(gemm_v, cudaFuncAttributeMaxDynamicSharedMemorySize, GM_SMEM);
    cudaFuncSetAttribute(gemm_qk, cudaFuncAttributeMaxDynamicSharedMemorySize, GM_SMEM);

    dim3 ggrid(EMB / BN, BATCH * SEQ / BM);          // (16, 32)
    dim3 qkgrid(EMB / BN, BATCH * SEQ / BM, 2);

    // 1: conversions
    cvt_f16_all<<<4096 + 4 * 2048, 256>>>(act, Wq, Wk, Wv, Wo);
    // 2: Q and K GEMMs with fused xpos -> fp16 qh/kh
    gemm_qk<<<qkgrid, 256, GM_SMEM>>>(acth, wqh, wkh, qh, kh);
    // 3: V GEMM -> fp16 vh
    gemm_v<<<ggrid, 256, GM_SMEM>>>(acth, wvh, vh);
    // 4: V transpose -> vth
    vtrans_kernel<<<32 * 64, 256>>>();
    // 5: attention
    attn_kernel<<<1024, 128>>>();
    // 6: output GEMM (ncu capture target)
    gemm_out<<<ggrid, 256, GM_SMEM>>>(atth, woh, out);
}